// round 2
// baseline (speedup 1.0000x reference)
#include <cuda_runtime.h>

// Problem constants
#define Bn 4
#define Ln 8
#define Nn 4096
#define Mn 2048
#define Kn 32
#define Sn 8
#define Jn 3

// Staging buffers (device globals; no runtime allocation)
__device__ float g_anchors[Bn * Sn * Mn * 3];            // anchor coords
__device__ float g_P[Bn * 8 * Nn * 64];                  // Ws0[:,:3]@xyz + Ws0[:,3:]@feat per point
__device__ float g_A[Bn * Sn * Mn * 64];                 // Ws0[:,:3]@anchor
__device__ int   g_idx[Bn * Sn * Jn * Mn * Kn];          // ball query result
__device__ float g_hmax[Bn * Sn * Jn * Mn * 128];        // [combo][m][r] max-pooled layer-1 out
__device__ float g_WtT[Jn * 128 * 256];                  // Wt transposed [j][r][o]
__device__ float g_Ws1T[64 * 128];                       // Ws1 transposed [k][r]

// ---------------------------------------------------------------------------
// K1: Furthest point sampling. One block per (b, s). 1024 threads, 4 pts each,
// all coords in registers; winner thread publishes coords via 3 shared floats.
// Arithmetic matches XLA: ((dx*dx + dy*dy) + dz*dz), no FMA contraction.
// argmax tie-break: smallest index.
// ---------------------------------------------------------------------------
__global__ void __launch_bounds__(1024) fps_kernel(const float* __restrict__ xyzs,
                                                   float* __restrict__ out_xyz) {
    int bs = blockIdx.x;
    const float* xyz = xyzs + (size_t)bs * Nn * 3;
    __shared__ float rv[32];
    __shared__ int ri[32];
    __shared__ int s_cur;
    __shared__ float scx, scy, scz;

    int t = threadIdx.x;
    int lane = t & 31, wid = t >> 5;

    float px[4], py[4], pz[4], pd[4];
#pragma unroll
    for (int i = 0; i < 4; i++) {
        int p = t + i * 1024;
        px[i] = xyz[3 * p]; py[i] = xyz[3 * p + 1]; pz[i] = xyz[3 * p + 2];
        pd[i] = 1e10f;
    }
    if (t == 0) { scx = px[0]; scy = py[0]; scz = pz[0]; }
    __syncthreads();

    float* oanc = g_anchors + (size_t)bs * Mn * 3;
    float* oxyz = out_xyz + (size_t)bs * Mn * 3;

    for (int m = 0; m < Mn; m++) {
        float cx = scx, cy = scy, cz = scz;
        if (t == 0) {
            oanc[3 * m] = cx; oanc[3 * m + 1] = cy; oanc[3 * m + 2] = cz;
            oxyz[3 * m] = cx; oxyz[3 * m + 1] = cy; oxyz[3 * m + 2] = cz;
        }
        float best = -1.0f;
        int bi = 0;
#pragma unroll
        for (int i = 0; i < 4; i++) {
            float dx = __fsub_rn(px[i], cx);
            float dy = __fsub_rn(py[i], cy);
            float dz = __fsub_rn(pz[i], cz);
            float d = __fadd_rn(__fadd_rn(__fmul_rn(dx, dx), __fmul_rn(dy, dy)),
                                __fmul_rn(dz, dz));
            float nd = fminf(pd[i], d);
            pd[i] = nd;
            if (nd > best) { best = nd; bi = t + i * 1024; }  // ascending => smallest idx on tie
        }
#pragma unroll
        for (int off = 16; off > 0; off >>= 1) {
            float v = __shfl_xor_sync(0xffffffffu, best, off);
            int j2 = __shfl_xor_sync(0xffffffffu, bi, off);
            if (v > best || (v == best && j2 < bi)) { best = v; bi = j2; }
        }
        if (lane == 0) { rv[wid] = best; ri[wid] = bi; }
        __syncthreads();
        if (wid == 0) {
            best = rv[lane]; bi = ri[lane];
#pragma unroll
            for (int off = 16; off > 0; off >>= 1) {
                float v = __shfl_xor_sync(0xffffffffu, best, off);
                int j2 = __shfl_xor_sync(0xffffffffu, bi, off);
                if (v > best || (v == best && j2 < bi)) { best = v; bi = j2; }
            }
            if (lane == 0) s_cur = bi;
        }
        __syncthreads();
        int cur = s_cur;
        int ii = cur >> 10;
        if ((cur & 1023) == t) { scx = px[ii]; scy = py[ii]; scz = pz[ii]; }
        __syncthreads();
    }
}

// ---------------------------------------------------------------------------
// K2a: P[b][f][n][64] = Ws0[:,0:3] @ xyz + Ws0[:,3:6] @ feat
// ---------------------------------------------------------------------------
__global__ void __launch_bounds__(256) compute_P(const float* __restrict__ xyzs,
                                                 const float* __restrict__ feats,
                                                 const float* __restrict__ Ws0) {
    __shared__ float w[64 * 6];
    int t = threadIdx.x;
    for (int i = t; i < 64 * 6; i += 256) w[i] = Ws0[i];
    __syncthreads();

    int gp = blockIdx.x * 256 + t;
    int n = gp & (Nn - 1);
    int bf = gp >> 12;
    const float* p = xyzs + (size_t)gp * 3;
    float x = p[0], y = p[1], z = p[2];
    const float* f = feats + (size_t)bf * 3 * Nn + n;
    float f0 = f[0], f1 = f[Nn], f2 = f[2 * Nn];
    float4* o = (float4*)(g_P + (size_t)gp * 64);
#pragma unroll
    for (int oo = 0; oo < 64; oo += 4) {
        float4 r;
        const float* w0 = w + oo * 6;
        r.x = w0[0] * x + w0[1] * y + w0[2] * z + w0[3] * f0 + w0[4] * f1 + w0[5] * f2;
        r.y = w0[6] * x + w0[7] * y + w0[8] * z + w0[9] * f0 + w0[10] * f1 + w0[11] * f2;
        r.z = w0[12] * x + w0[13] * y + w0[14] * z + w0[15] * f0 + w0[16] * f1 + w0[17] * f2;
        r.w = w0[18] * x + w0[19] * y + w0[20] * z + w0[21] * f0 + w0[22] * f1 + w0[23] * f2;
        o[oo >> 2] = r;
    }
}

// ---------------------------------------------------------------------------
// K2b: A[b][s][m][64] = Ws0[:,0:3] @ anchor
// ---------------------------------------------------------------------------
__global__ void __launch_bounds__(256) compute_A(const float* __restrict__ Ws0) {
    __shared__ float w[64 * 3];
    int t = threadIdx.x;
    for (int i = t; i < 64 * 3; i += 256) {
        int o = i / 3, c = i % 3;
        w[i] = Ws0[o * 6 + c];
    }
    __syncthreads();
    int ga = blockIdx.x * 256 + t;
    const float* a = g_anchors + (size_t)ga * 3;
    float x = a[0], y = a[1], z = a[2];
    float4* o = (float4*)(g_A + (size_t)ga * 64);
#pragma unroll
    for (int oo = 0; oo < 64; oo += 4) {
        float4 r;
        const float* w0 = w + oo * 3;
        r.x = w0[0] * x + w0[1] * y + w0[2] * z;
        r.y = w0[3] * x + w0[4] * y + w0[5] * z;
        r.z = w0[6] * x + w0[7] * y + w0[8] * z;
        r.w = w0[9] * x + w0[10] * y + w0[11] * z;
        o[oo >> 2] = r;
    }
}

// ---------------------------------------------------------------------------
// K2c: transpose Wt[j][o][r] -> WtT[j][r][o]; transpose Ws1[r][k] -> Ws1T[k][r]
// ---------------------------------------------------------------------------
__global__ void __launch_bounds__(256) transpose_weights(const float* __restrict__ Wt,
                                                         const float* __restrict__ Ws1) {
    int t = blockIdx.x * 256 + threadIdx.x;
    if (t < Jn * 256 * 128) {
        int j = t / (256 * 128);
        int rem = t % (256 * 128);
        int o = rem / 128, r = rem % 128;
        g_WtT[(j * 128 + r) * 256 + o] = Wt[t];
    }
    if (t < 128 * 64) {
        int r = t >> 6, k = t & 63;
        g_Ws1T[k * 128 + r] = Ws1[t];
    }
}

// ---------------------------------------------------------------------------
// K3: ball query. One warp per anchor; first-32 in ascending index order,
// pad with first found (0 if none).
// ---------------------------------------------------------------------------
__global__ void __launch_bounds__(256) ball_query_kernel(const float* __restrict__ xyzs) {
    int combo = blockIdx.y;  // ((b*8+s)*3 + j)
    int j = combo % 3;
    int bs = combo / 3;
    int b = bs >> 3, s = bs & 7;
    int g = s - 1 + j;
    g = g < 0 ? 0 : (g > 7 ? 7 : g);
    int wid = threadIdx.x >> 5, lane = threadIdx.x & 31;
    int m = blockIdx.x * 8 + wid;

    const float* pts = xyzs + (size_t)(b * 8 + g) * Nn * 3;
    const float* anc = g_anchors + ((size_t)bs * Mn + m) * 3;
    float ax = anc[0], ay = anc[1], az = anc[2];
    int* out = g_idx + ((size_t)combo * Mn + m) * Kn;

    int found = 0, first = -1;
    unsigned lt = (1u << lane) - 1u;
    for (int base = 0; base < Nn && found < Kn; base += 32) {
        int n = base + lane;
        const float* pp = pts + 3 * n;
        float dx = __fsub_rn(pp[0], ax);
        float dy = __fsub_rn(pp[1], ay);
        float dz = __fsub_rn(pp[2], az);
        float d2 = __fadd_rn(__fadd_rn(__fmul_rn(dx, dx), __fmul_rn(dy, dy)),
                             __fmul_rn(dz, dz));
        bool pred = d2 < 0.25f;
        unsigned msk = __ballot_sync(0xffffffffu, pred);
        if (first < 0 && msk) first = base + (__ffs(msk) - 1);
        int pos = found + __popc(msk & lt);
        if (pred && pos < Kn) out[pos] = n;
        found += __popc(msk);
    }
    if (found < Kn) {
        int pad = first < 0 ? 0 : first;
        for (int p = found + lane; p < Kn; p += 32) out[p] = pad;
    }
}

// ---------------------------------------------------------------------------
// K4: layer-1 GEMM fused with h0 generation (relu(P[n]-A[m])), relu, 32-way
// max pool. Tile: 128 rows x 64 cols, K=64. 256 threads, 4x8 microtile with
// split columns (c0, c0+32) for conflict-free LDS. Static smem = 48KB exactly.
// ---------------------------------------------------------------------------
__global__ void __launch_bounds__(256) mlp_kernel() {
    __shared__ float Wsh[64 * 128];  // Wsh[k][r]
    __shared__ float Hsh[64 * 64];   // Hsh[k][c]

    int t = threadIdx.x;
    int combo = blockIdx.y;
    int j = combo % 3;
    int bs = combo / 3;
    int b = bs >> 3, s = bs & 7;
    int g = s - 1 + j;
    g = g < 0 ? 0 : (g > 7 ? 7 : g);

    // load Ws1T (already [k][r]) — fully coalesced LDG + conflict-free STS
    for (int i = t; i < 64 * 128; i += 256) Wsh[i] = g_Ws1T[i];

    // producer: H0 tile cols = 2 anchors x 32 neighbors
    {
        int col = t & 63;
        int quarter = t >> 6;  // k-range quarter*16 .. +15
        int gcol = blockIdx.x * 64 + col;
        int m = gcol >> 5;
        int knb = gcol & 31;
        int n = g_idx[((size_t)combo * Mn + m) * Kn + knb];
        const float4* Prow = (const float4*)(g_P + ((size_t)(b * 8 + g) * Nn + n) * 64) + quarter * 4;
        const float4* Arow = (const float4*)(g_A + ((size_t)bs * Mn + m) * 64) + quarter * 4;
#pragma unroll
        for (int q = 0; q < 4; q++) {
            float4 p4 = Prow[q];
            float4 a4 = Arow[q];
            int c = quarter * 16 + q * 4;
            Hsh[(c + 0) * 64 + col] = fmaxf(p4.x - a4.x, 0.f);
            Hsh[(c + 1) * 64 + col] = fmaxf(p4.y - a4.y, 0.f);
            Hsh[(c + 2) * 64 + col] = fmaxf(p4.z - a4.z, 0.f);
            Hsh[(c + 3) * 64 + col] = fmaxf(p4.w - a4.w, 0.f);
        }
    }
    __syncthreads();

    // GEMM mainloop: rows r0..r0+3, cols {c0..c0+3, c0+32..c0+35}
    int r0 = (t >> 3) << 2;       // 0..124
    int c0 = (t & 7) << 2;        // 0..28
    float acc[4][8];
#pragma unroll
    for (int a = 0; a < 4; a++)
#pragma unroll
        for (int bb = 0; bb < 8; bb++) acc[a][bb] = 0.f;

#pragma unroll 8
    for (int k = 0; k < 64; k++) {
        float4 av = *(const float4*)&Wsh[k * 128 + r0];
        float4 b0 = *(const float4*)&Hsh[k * 64 + c0];
        float4 b1 = *(const float4*)&Hsh[k * 64 + c0 + 32];
        float a4[4] = {av.x, av.y, av.z, av.w};
        float bv[8] = {b0.x, b0.y, b0.z, b0.w, b1.x, b1.y, b1.z, b1.w};
#pragma unroll
        for (int rr = 0; rr < 4; rr++)
#pragma unroll
            for (int cc = 0; cc < 8; cc++) acc[rr][cc] += a4[rr] * bv[cc];
    }
    __syncthreads();

    // epilogue: alias hmax scratch over Hsh (no longer needed)
    int* hmi = (int*)Hsh;  // [2 anchors][128 rows]
    hmi[t] = 0;
    __syncthreads();
#pragma unroll
    for (int rr = 0; rr < 4; rr++) {
        float mx0 = fmaxf(fmaxf(acc[rr][0], acc[rr][1]), fmaxf(acc[rr][2], acc[rr][3]));
        float mx1 = fmaxf(fmaxf(acc[rr][4], acc[rr][5]), fmaxf(acc[rr][6], acc[rr][7]));
        mx0 = fmaxf(mx0, 0.f);
        mx1 = fmaxf(mx1, 0.f);
        atomicMax(&hmi[r0 + rr], __float_as_int(mx0));
        atomicMax(&hmi[128 + r0 + rr], __float_as_int(mx1));
    }
    __syncthreads();

    // write [combo][m][r] — coalesced
    int mbase = blockIdx.x * 2;
    int a = t >> 7, r = t & 127;
    g_hmax[((size_t)combo * Mn + mbase + a) * 128 + r] = __int_as_float(hmi[a * 128 + r]);
}

// ---------------------------------------------------------------------------
// K5: out[b][s][o][m] = sum_j relu(Wt[j] @ hmax[b][s][j]).
// Block: 256 output rows x 32 anchors. hsh layout [mm][r], all loads coalesced.
// ---------------------------------------------------------------------------
__global__ void __launch_bounds__(256) wt_kernel(float* __restrict__ outf) {
    __shared__ float hsh[32 * 128];
    int t = threadIdx.x;
    int bs = blockIdx.y;
    int mbase = blockIdx.x * 32;

    float tot[32];
#pragma unroll
    for (int i = 0; i < 32; i++) tot[i] = 0.f;

    for (int j = 0; j < 3; j++) {
        const float* hb = g_hmax + ((size_t)(bs * 3 + j) * Mn + mbase) * 128;
        for (int i = t; i < 32 * 128; i += 256) hsh[i] = hb[i];
        __syncthreads();

        float acc[32];
#pragma unroll
        for (int i = 0; i < 32; i++) acc[i] = 0.f;

        const float* wtb = g_WtT + (size_t)j * 128 * 256 + t;
        for (int r = 0; r < 128; r += 4) {
            float w0 = wtb[(r + 0) * 256];
            float w1 = wtb[(r + 1) * 256];
            float w2 = wtb[(r + 2) * 256];
            float w3 = wtb[(r + 3) * 256];
#pragma unroll
            for (int mm = 0; mm < 32; mm++) {
                float4 h = *(const float4*)&hsh[mm * 128 + r];
                acc[mm] += w0 * h.x + w1 * h.y + w2 * h.z + w3 * h.w;
            }
        }
#pragma unroll
        for (int i = 0; i < 32; i++) tot[i] += fmaxf(acc[i], 0.f);
        __syncthreads();
    }

    float4* o = (float4*)(outf + ((size_t)bs * 256 + t) * Mn + mbase);
#pragma unroll
    for (int q = 0; q < 8; q++) {
        float4 r;
        r.x = tot[4 * q + 0];
        r.y = tot[4 * q + 1];
        r.z = tot[4 * q + 2];
        r.w = tot[4 * q + 3];
        o[q] = r;
    }
}

// ---------------------------------------------------------------------------
extern "C" void kernel_launch(void* const* d_in, const int* in_sizes, int n_in,
                              void* d_out, int out_size) {
    const float* xyzs = (const float*)d_in[0];
    const float* feats = (const float*)d_in[1];
    const float* Ws0 = (const float*)d_in[2];
    const float* Ws1 = (const float*)d_in[3];
    const float* Wt = (const float*)d_in[4];
    float* out = (float*)d_out;

    const int XYZ_TOTAL = Bn * Sn * Mn * 3;  // 196608

    fps_kernel<<<Bn * Sn, 1024>>>(xyzs, out);
    compute_P<<<Bn * 8 * Nn / 256, 256>>>(xyzs, feats, Ws0);
    transpose_weights<<<(Jn * 256 * 128 + 255) / 256, 256>>>(Wt, Ws1);
    compute_A<<<Bn * Sn * Mn / 256, 256>>>(Ws0);
    ball_query_kernel<<<dim3(Mn / 8, Bn * Sn * Jn), 256>>>(xyzs);
    mlp_kernel<<<dim3(Mn * Kn / 64, Bn * Sn * Jn), 256>>>();
    wt_kernel<<<dim3(Mn / 32, Bn * Sn), 256>>>(out + XYZ_TOTAL);
}